// round 16
// baseline (speedup 1.0000x reference)
#include <cuda_runtime.h>
#include <cuda_bf16.h>
#include <math.h>
#include <cstdint>

#define Bsz 4
#define Tsz 4096
#define Dsz 1024
#define Hsz 4
#define DKsz 256
#define DVsz 256
#define ROWS (Bsz*Tsz)
#define CH 64
#define NCH (Tsz/CH)

// -------- static device scratch --------
__device__ float g_q[ROWS * Dsz];
__device__ float g_k[ROWS * Dsz];
__device__ float g_v[ROWS * Dsz];
__device__ float g_g[ROWS * Dsz];
__device__ float g_o[ROWS * Dsz];
__device__ float g_beta[ROWS * Hsz];
__device__ float g_dec[ROWS * Hsz];
__device__ float g_minv[16 * NCH * CH * CH];
__device__ float g_pmat[16 * NCH * CH * CH];   // holds R = P*Minv
__device__ float g_coef[16 * NCH * 256];
__device__ __nv_bfloat16 g_xh[ROWS * Dsz];
__device__ __nv_bfloat16 g_xl[ROWS * Dsz];
__device__ __nv_bfloat16 g_yh[ROWS * Dsz];
__device__ __nv_bfloat16 g_yl[ROWS * Dsz];
__device__ __nv_bfloat16 g_qh[ROWS * Dsz];
__device__ __nv_bfloat16 g_ql[ROWS * Dsz];
__device__ __nv_bfloat16 g_kh[ROWS * Dsz];
__device__ __nv_bfloat16 g_kl[ROWS * Dsz];
__device__ __nv_bfloat16 g_kth[16 * DKsz * Tsz];
__device__ __nv_bfloat16 g_ktl[16 * DKsz * Tsz];
__device__ __nv_bfloat16 g_wth[5 * Dsz * Dsz];
__device__ __nv_bfloat16 g_wtl[5 * Dsz * Dsz];

// ---- helpers ----
__device__ __forceinline__ uint32_t smem_to_u32(const void* p) {
    uint32_t a;
    asm("{ .reg .u64 t; cvta.to.shared.u64 t, %1; cvt.u32.u64 %0, t; }"
        : "=r"(a) : "l"(p));
    return a;
}
__device__ __forceinline__ void cp_async16(uint32_t s, const void* g) {
    asm volatile("cp.async.cg.shared.global [%0], [%1], 16;" :: "r"(s), "l"(g));
}
__device__ __forceinline__ void ldsm4(uint32_t& r0, uint32_t& r1, uint32_t& r2,
                                      uint32_t& r3, uint32_t addr) {
    asm volatile("ldmatrix.sync.aligned.m8n8.x4.shared.b16 {%0,%1,%2,%3}, [%4];"
                 : "=r"(r0), "=r"(r1), "=r"(r2), "=r"(r3) : "r"(addr));
}
__device__ __forceinline__ void ldsm4p(uint32_t* r, uint32_t addr) {
    ldsm4(r[0], r[1], r[2], r[3], addr);
}
__device__ __forceinline__ void mma16816(float* c, const uint32_t* a,
                                         uint32_t b0, uint32_t b1) {
    asm volatile(
        "mma.sync.aligned.m16n8k16.row.col.f32.bf16.bf16.f32 "
        "{%0,%1,%2,%3}, {%4,%5,%6,%7}, {%8,%9}, {%0,%1,%2,%3};"
        : "+f"(c[0]), "+f"(c[1]), "+f"(c[2]), "+f"(c[3])
        : "r"(a[0]), "r"(a[1]), "r"(a[2]), "r"(a[3]), "r"(b0), "r"(b1));
}
__device__ __forceinline__ __nv_bfloat162 splitpack2(float a, float b,
                                                     __nv_bfloat162& lo) {
    __nv_bfloat16 h0 = __float2bfloat16(a), h1 = __float2bfloat16(b);
    lo = __halves2bfloat162(__float2bfloat16(a - __bfloat162float(h0)),
                            __float2bfloat16(b - __bfloat162float(h1)));
    return __halves2bfloat162(h0, h1);
}

// ---- fp32 -> hi/lo bf16 split ----
__global__ __launch_bounds__(256) void split_kernel(
    const float* __restrict__ src, __nv_bfloat16* __restrict__ hi,
    __nv_bfloat16* __restrict__ lo)
{
    const int i = blockIdx.x * 256 + threadIdx.x;
    float4 v = ((const float4*)src)[i];
    __nv_bfloat162 l0, l1;
    __nv_bfloat162 h0 = splitpack2(v.x, v.y, l0);
    __nv_bfloat162 h1 = splitpack2(v.z, v.w, l1);
    ((__nv_bfloat162*)hi)[i*2]   = h0;
    ((__nv_bfloat162*)hi)[i*2+1] = h1;
    ((__nv_bfloat162*)lo)[i*2]   = l0;
    ((__nv_bfloat162*)lo)[i*2+1] = l1;
}

// ---- transpose 1024x1024 weight + split ----
__global__ __launch_bounds__(256) void transpose_split_kernel(
    const float* __restrict__ W, __nv_bfloat16* __restrict__ Th,
    __nv_bfloat16* __restrict__ Tl)
{
    __shared__ float tile[32][33];
    const int n0 = blockIdx.x * 32, k0 = blockIdx.y * 32;
    const int tx = threadIdx.x & 31, ty = threadIdx.x >> 5;
#pragma unroll
    for (int r = ty; r < 32; r += 8)
        tile[r][tx] = W[(size_t)(k0 + r) * Dsz + n0 + tx];
    __syncthreads();
#pragma unroll
    for (int r = ty; r < 32; r += 8) {
        float v = tile[tx][r];
        __nv_bfloat16 h = __float2bfloat16(v);
        __nv_bfloat16 l = __float2bfloat16(v - __bfloat162float(h));
        size_t o = (size_t)(n0 + r) * Dsz + k0 + tx;
        Th[o] = h; Tl[o] = l;
    }
}

// ---- transpose k per bh -> KT [bh][256 dk][4096 t] hi/lo bf16 ----
__global__ __launch_bounds__(256) void transpose_k_kernel(
    const float* __restrict__ k, __nv_bfloat16* __restrict__ kth,
    __nv_bfloat16* __restrict__ ktl)
{
    __shared__ float tile[32][33];
    const int tblk = blockIdx.x * 32, dkblk = blockIdx.y * 32;
    const int bh = blockIdx.z, b = bh >> 2, h = bh & 3;
    const int tx = threadIdx.x & 31, ty = threadIdx.x >> 5;
    const size_t rowbase = (size_t)b * Tsz * Dsz + h * DKsz;
#pragma unroll
    for (int r = ty; r < 32; r += 8)
        tile[r][tx] = k[rowbase + (size_t)(tblk + r) * Dsz + dkblk + tx];
    __syncthreads();
#pragma unroll
    for (int r = ty; r < 32; r += 8) {
        float v = tile[tx][r];
        __nv_bfloat16 h2 = __float2bfloat16(v);
        __nv_bfloat16 l2 = __float2bfloat16(v - __bfloat162float(h2));
        size_t o = ((size_t)bh * DKsz + dkblk + r) * Tsz + tblk + tx;
        kth[o] = h2; ktl[o] = l2;
    }
}

// ============================================================
// bf16x3 GEMM (verified R11/R12)
// ============================================================
#define TILE_BYTES (128*80)
#define STAGE_BYTES (4*TILE_BYTES)
#define GEMM_SMEM (2*STAGE_BYTES)

__device__ __forceinline__ void gemm_body(
    const __nv_bfloat16* srcA_h, const __nv_bfloat16* srcA_l,
    const __nv_bfloat16* srcB_h, const __nv_bfloat16* srcB_l,
    float* Cb, char* sm)
{
    const int tid = threadIdx.x;
    const int wid = tid >> 5, lane = tid & 31;
    const int wm = wid & 3, wn = wid >> 2;
    const uint32_t sbase = smem_to_u32(sm);
    const __nv_bfloat16* srcs[4] = { srcA_h, srcA_l, srcB_h, srcB_l };
    float acc[2][8][4];
#pragma unroll
    for (int mt = 0; mt < 2; mt++)
#pragma unroll
        for (int nt = 0; nt < 8; nt++)
#pragma unroll
            for (int i = 0; i < 4; i++) acc[mt][nt][i] = 0.f;
    auto load_stage = [&](int kc) {
        const uint32_t sdst = sbase + (kc & 1) * STAGE_BYTES;
        const int k0 = kc * 32;
#pragma unroll
        for (int t = 0; t < 4; t++) {
#pragma unroll
            for (int i = 0; i < 2; i++) {
                int id = i * 256 + tid;
                int r = id >> 2, c = id & 3;
                cp_async16(sdst + t * TILE_BYTES + r * 80 + c * 16,
                           srcs[t] + (size_t)r * Dsz + k0 + c * 8);
            }
        }
        asm volatile("cp.async.commit_group;" ::: "memory");
    };
    load_stage(0);
    const int lrow = lane & 15, lcolb = (lane >> 4) * 16;
    for (int kc = 0; kc < 32; kc++) {
        if (kc < 31) load_stage(kc + 1);
        else asm volatile("cp.async.commit_group;" ::: "memory");
        asm volatile("cp.async.wait_group 1;" ::: "memory");
        __syncthreads();
        const uint32_t s = sbase + (kc & 1) * STAGE_BYTES;
#pragma unroll
        for (int ks = 0; ks < 2; ks++) {
            const uint32_t cb = ks * 32 + lcolb;
            uint32_t ah[2][4], bh[4][4], al[2][4], bl[4][4];
#pragma unroll
            for (int mt = 0; mt < 2; mt++)
                ldsm4p(ah[mt], s + (wm * 32 + mt * 16 + lrow) * 80 + cb);
#pragma unroll
            for (int bt = 0; bt < 4; bt++)
                ldsm4p(bh[bt], s + 2*TILE_BYTES + (wn * 64 + bt * 16 + lrow) * 80 + cb);
#pragma unroll
            for (int mt = 0; mt < 2; mt++)
#pragma unroll
                for (int bt = 0; bt < 4; bt++) {
                    mma16816(acc[mt][bt*2],   ah[mt], bh[bt][0], bh[bt][2]);
                    mma16816(acc[mt][bt*2+1], ah[mt], bh[bt][1], bh[bt][3]);
                }
#pragma unroll
            for (int mt = 0; mt < 2; mt++)
                ldsm4p(al[mt], s + TILE_BYTES + (wm * 32 + mt * 16 + lrow) * 80 + cb);
#pragma unroll
            for (int mt = 0; mt < 2; mt++)
#pragma unroll
                for (int bt = 0; bt < 4; bt++) {
                    mma16816(acc[mt][bt*2],   al[mt], bh[bt][0], bh[bt][2]);
                    mma16816(acc[mt][bt*2+1], al[mt], bh[bt][1], bh[bt][3]);
                }
#pragma unroll
            for (int bt = 0; bt < 4; bt++)
                ldsm4p(bl[bt], s + 3*TILE_BYTES + (wn * 64 + bt * 16 + lrow) * 80 + cb);
#pragma unroll
            for (int mt = 0; mt < 2; mt++)
#pragma unroll
                for (int bt = 0; bt < 4; bt++) {
                    mma16816(acc[mt][bt*2],   ah[mt], bl[bt][0], bl[bt][2]);
                    mma16816(acc[mt][bt*2+1], ah[mt], bl[bt][1], bl[bt][3]);
                }
        }
        __syncthreads();
    }
    const int crow = wm * 32 + (lane >> 2);
    const int ccol = wn * 64 + (lane & 3) * 2;
#pragma unroll
    for (int mt = 0; mt < 2; mt++)
#pragma unroll
        for (int nt = 0; nt < 8; nt++) {
            float* p0 = Cb + (size_t)(crow + mt * 16) * Dsz + ccol + nt * 8;
            *(float2*)p0 = make_float2(acc[mt][nt][0], acc[mt][nt][1]);
            *(float2*)(p0 + 8 * Dsz) = make_float2(acc[mt][nt][2], acc[mt][nt][3]);
        }
}

__global__ __launch_bounds__(256, 2) void gemm_mma_bf16x3(
    const __nv_bfloat16* __restrict__ Ah, const __nv_bfloat16* __restrict__ Al,
    const __nv_bfloat16* __restrict__ Bh, const __nv_bfloat16* __restrict__ Bl,
    float* __restrict__ C)
{
    extern __shared__ char sm[];
    const int bx = blockIdx.x, by = blockIdx.y;
    gemm_body(Ah + (size_t)(by * 128) * Dsz, Al + (size_t)(by * 128) * Dsz,
              Bh + (size_t)(bx * 128) * Dsz, Bl + (size_t)(bx * 128) * Dsz,
              C + (size_t)(by * 128) * Dsz + bx * 128, sm);
}

__global__ __launch_bounds__(256, 2) void gemm_mega4(
    const __nv_bfloat16* __restrict__ Ah, const __nv_bfloat16* __restrict__ Al,
    const __nv_bfloat16* __restrict__ Wth, const __nv_bfloat16* __restrict__ Wtl,
    float* __restrict__ C0, float* __restrict__ C1,
    float* __restrict__ C2, float* __restrict__ C3)
{
    extern __shared__ char sm[];
    const int bx = blockIdx.x, by = blockIdx.y;
    const int m = bx >> 3, bxl = bx & 7;
    float* Cm = (m == 0) ? C0 : (m == 1) ? C1 : (m == 2) ? C2 : C3;
    const size_t woff = (size_t)m * Dsz * Dsz + (size_t)(bxl * 128) * Dsz;
    gemm_body(Ah + (size_t)(by * 128) * Dsz, Al + (size_t)(by * 128) * Dsz,
              Wth + woff, Wtl + woff,
              Cm + (size_t)(by * 128) * Dsz + bxl * 128, sm);
}

// ---- beta/dec ----
__global__ __launch_bounds__(256) void beta_dec_kernel(
    const float* __restrict__ x, const float* __restrict__ Wb,
    const float* __restrict__ Wa, const float* __restrict__ A_log,
    const float* __restrict__ dt_bias,
    float* __restrict__ beta, float* __restrict__ dec)
{
    const int row = blockIdx.x * 8 + (threadIdx.x >> 5);
    const int lane = threadIdx.x & 31;
    float accb[4] = {0,0,0,0}, acca[4] = {0,0,0,0};
    const float* xr = x + (size_t)row * Dsz;
    const float4* Wb4 = (const float4*)Wb;
    const float4* Wa4 = (const float4*)Wa;
    for (int i = lane; i < Dsz; i += 32) {
        float xv = xr[i];
        float4 wb = Wb4[i], wa = Wa4[i];
        accb[0] += xv*wb.x; accb[1] += xv*wb.y; accb[2] += xv*wb.z; accb[3] += xv*wb.w;
        acca[0] += xv*wa.x; acca[1] += xv*wa.y; acca[2] += xv*wa.z; acca[3] += xv*wa.w;
    }
#pragma unroll
    for (int off = 16; off; off >>= 1)
#pragma unroll
        for (int h = 0; h < 4; h++) {
            accb[h] += __shfl_xor_sync(0xffffffffu, accb[h], off);
            acca[h] += __shfl_xor_sync(0xffffffffu, acca[h], off);
        }
    if (lane < 4) {
        int h = lane;
        float bv = 1.f / (1.f + expf(-accb[h]));
        float a = acca[h] + dt_bias[h];
        float sp = fmaxf(a, 0.f) + log1pf(expf(-fabsf(a)));
        beta[(size_t)row * Hsz + h] = bv;
        dec [(size_t)row * Hsz + h] = expf(-expf(A_log[h]) * sp);
    }
}

// ---- L2 norm q/k, fused hi/lo bf16 split output ----
__global__ __launch_bounds__(256) void norm_qk_split_kernel(
    float* __restrict__ q, float* __restrict__ k,
    __nv_bfloat16* __restrict__ qh, __nv_bfloat16* __restrict__ ql,
    __nv_bfloat16* __restrict__ kh, __nv_bfloat16* __restrict__ kl)
{
    const int row = blockIdx.x * 8 + (threadIdx.x >> 5);
    const int lane = threadIdx.x & 31;
    float4* qr = (float4*)(q + (size_t)row * DKsz);
    float4* kr = (float4*)(k + (size_t)row * DKsz);
    float4 q0 = qr[lane*2], q1 = qr[lane*2+1], k0 = kr[lane*2], k1 = kr[lane*2+1];
    float sq = q0.x*q0.x+q0.y*q0.y+q0.z*q0.z+q0.w*q0.w+q1.x*q1.x+q1.y*q1.y+q1.z*q1.z+q1.w*q1.w;
    float sk = k0.x*k0.x+k0.y*k0.y+k0.z*k0.z+k0.w*k0.w+k1.x*k1.x+k1.y*k1.y+k1.z*k1.z+k1.w*k1.w;
#pragma unroll
    for (int off = 16; off; off >>= 1) {
        sq += __shfl_xor_sync(0xffffffffu, sq, off);
        sk += __shfl_xor_sync(0xffffffffu, sk, off);
    }
    float qs = rsqrtf(sq + 1e-6f) * 0.0625f;
    float ks = rsqrtf(sk + 1e-6f);
    q0.x*=qs;q0.y*=qs;q0.z*=qs;q0.w*=qs; q1.x*=qs;q1.y*=qs;q1.z*=qs;q1.w*=qs;
    k0.x*=ks;k0.y*=ks;k0.z*=ks;k0.w*=ks; k1.x*=ks;k1.y*=ks;k1.z*=ks;k1.w*=ks;
    qr[lane*2]=q0; qr[lane*2+1]=q1; kr[lane*2]=k0; kr[lane*2+1]=k1;
    const size_t e0 = (size_t)row * DKsz + lane * 8;
    __nv_bfloat162 lo;
    ((__nv_bfloat162*)(qh + e0))[0] = splitpack2(q0.x, q0.y, lo); ((__nv_bfloat162*)(ql + e0))[0] = lo;
    ((__nv_bfloat162*)(qh + e0))[1] = splitpack2(q0.z, q0.w, lo); ((__nv_bfloat162*)(ql + e0))[1] = lo;
    ((__nv_bfloat162*)(qh + e0))[2] = splitpack2(q1.x, q1.y, lo); ((__nv_bfloat162*)(ql + e0))[2] = lo;
    ((__nv_bfloat162*)(qh + e0))[3] = splitpack2(q1.z, q1.w, lo); ((__nv_bfloat162*)(ql + e0))[3] = lo;
    ((__nv_bfloat162*)(kh + e0))[0] = splitpack2(k0.x, k0.y, lo); ((__nv_bfloat162*)(kl + e0))[0] = lo;
    ((__nv_bfloat162*)(kh + e0))[1] = splitpack2(k0.z, k0.w, lo); ((__nv_bfloat162*)(kl + e0))[1] = lo;
    ((__nv_bfloat162*)(kh + e0))[2] = splitpack2(k1.x, k1.y, lo); ((__nv_bfloat162*)(kl + e0))[2] = lo;
    ((__nv_bfloat162*)(kh + e0))[3] = splitpack2(k1.z, k1.w, lo); ((__nv_bfloat162*)(kl + e0))[3] = lo;
}

// ============================================================
// Kernel A: UT-transform precompute + R = P*Minv fusion.
// pmat now stores R (so the scan's O phase is independent of U).
// ============================================================
#define UTP_SMEM 164352
__device__ __forceinline__ int swz(int row, int f4i) {
    return row * 64 + (f4i ^ ((row >> 2) & 7));
}
__global__ __launch_bounds__(256) void ut_prep(
    const float* __restrict__ k, const float* __restrict__ q,
    const float* __restrict__ beta, const float* __restrict__ dec,
    float* __restrict__ minv, float* __restrict__ pmat, float* __restrict__ coef)
{
    extern __shared__ float sA[];
    float* sk = sA;                 // [64][256] swizzled; later sP [64][65]
    float* sq = sA + 16384;
    float* w1 = sA + 32768;         // KK -> negW
    float* w2 = w1 + 4096;          // QK -> Minv
    float* sdec = w2 + 4096;
    float* sbeta = sdec + 64;
    float* sP = sA;                 // P, stride 65 (reuses sk after dots)
    const int ch = blockIdx.x, bh = blockIdx.y;
    const int b = bh >> 2, h = bh & 3;
    const int tid = threadIdx.x, t0 = ch * CH;
    const size_t rowbase = (size_t)b * Tsz * Dsz + h * DKsz;
#pragma unroll
    for (int r = 0; r < 16; r++) {
        int idx = r * 256 + tid;
        int row = idx >> 6, f4i = idx & 63;
        float4 kv = *(const float4*)(k + rowbase + (size_t)(t0+row)*Dsz + f4i*4);
        float4 qv = *(const float4*)(q + rowbase + (size_t)(t0+row)*Dsz + f4i*4);
        *(float4*)&sk[swz(row, f4i)*4] = kv;
        *(float4*)&sq[swz(row, f4i)*4] = qv;
    }
    if (tid < CH) {
        size_t bidx = (size_t)(b * Tsz + t0 + tid) * Hsz + h;
        sdec[tid] = dec[bidx];
        sbeta[tid] = beta[bidx];
    }
    __syncthreads();
    {
        const int i0 = (tid >> 4) * 4, j0 = (tid & 15) * 4;
        float aK[4][4] = {}, aQ[4][4] = {};
        for (int cc = 0; cc < 64; cc++) {
            float4 kj[4], ki[4], qi[4];
#pragma unroll
            for (int a = 0; a < 4; a++) {
                kj[a] = *(const float4*)&sk[swz(j0+a, cc)*4];
                ki[a] = *(const float4*)&sk[swz(i0+a, cc)*4];
                qi[a] = *(const float4*)&sq[swz(i0+a, cc)*4];
            }
#pragma unroll
            for (int a = 0; a < 4; a++)
#pragma unroll
                for (int bb = 0; bb < 4; bb++) {
                    aK[a][bb] += ki[a].x*kj[bb].x + ki[a].y*kj[bb].y
                               + ki[a].z*kj[bb].z + ki[a].w*kj[bb].w;
                    aQ[a][bb] += qi[a].x*kj[bb].x + qi[a].y*kj[bb].y
                               + qi[a].z*kj[bb].z + qi[a].w*kj[bb].w;
                }
        }
        __syncthreads();   // sk/sq reads done; sP may alias sk
#pragma unroll
        for (int a = 0; a < 4; a++)
#pragma unroll
            for (int bb = 0; bb < 4; bb++) {
                w1[(i0+a)*64 + j0+bb] = aK[a][bb];
                w2[(i0+a)*64 + j0+bb] = aQ[a][bb];
            }
    }
    __syncthreads();
    // scale rows -> P (smem, stride 65) and negW; coefs
    if (tid < CH) {
        const int i = tid;
        const float bi = sbeta[i];
        float gam = 1.f;
        for (int m = 0; m <= i; m++) gam *= sdec[m];
        float ccv = 1.f;
        for (int m = i + 1; m < CH; m++) ccv *= sdec[m];
        float* cf = coef + (size_t)(bh * NCH + ch) * 256;
        cf[i] = bi; cf[64+i] = bi * gam; cf[128+i] = gam; cf[192+i] = ccv;
        float ratio = 1.f;
        for (int j = i; j >= 0; j--) {
            if (j < i) ratio *= sdec[j + 1];
            sP[i*65 + j] = ratio * w2[i*64 + j];
            w1[i*64 + j] = (j < i) ? (-bi * ratio * w1[i*64 + j]) : 0.f;
        }
        for (int j = i + 1; j < CH; j++) sP[i*65 + j] = 0.f;
    }
    __syncthreads();
    // Minv columns (forward substitution) into w2
    if (tid < CH) {
        const int j = tid;
        for (int i = 0; i < j; i++) w2[i*64 + j] = 0.f;
        w2[j*64 + j] = 1.f;
        for (int i = j + 1; i < CH; i++) {
            float s = w1[i*64 + j];
            for (int m = j + 1; m < i; m++) s += w1[i*64 + m] * w2[m*64 + j];
            w2[i*64 + j] = s;
        }
    }
    __syncthreads();
    // R = P * Minv  -> pmat  (dense 64x64, fp32)
    {
        const int i = tid >> 2;           // 0..63
        const int j0 = (tid & 3) * 16;    // 16 cols
        float racc[16];
#pragma unroll
        for (int c = 0; c < 16; c++) racc[c] = 0.f;
        for (int m = 0; m < 64; m++) {
            float pv = sP[i*65 + m];
            const float* mrow = &w2[m*64 + j0];
#pragma unroll
            for (int c = 0; c < 16; c++) racc[c] += pv * mrow[c];
        }
        float* prow = pmat + (size_t)(bh * NCH + ch) * 4096 + i * 64 + j0;
#pragma unroll
        for (int c = 0; c < 16; c++) prow[c] = racc[c];
    }
#pragma unroll
    for (int r = 0; r < 16; r++) {
        int idx = r * 256 + tid;
        minv[(size_t)(bh * NCH + ch) * 4096 + idx] = w2[idx];
    }
}

// ============================================================
// Kernel B: 512-thread serial chunk scan; merged UO phase
// (warps 0-7: O = gam*Z + R*B' -> gmem; warps 8-15: U = Minv*B'
//  packed directly to Ut hi/lo). One fewer phase per chunk.
// ============================================================
#define SB_STH  0
#define SB_STL  16896
#define SB_KQ   33792
#define SB_KQLO (SB_KQ + 67584)
#define SB_KT   SB_KQ
#define SB_KTLO (SB_KQ + 36864)
#define SB_MINV (SB_KQ + 73728)
#define SB_PMAT (SB_KQ + 90112)
#define SB_M0   168960
#define SB_Z0   177152
#define SB_M1   185344
#define SB_Z1   193536
#define SB_UTH  201728
#define SB_UTL  206336
#define SB_CF   210944
#define SB_V    211968
#define SCAN_SMEM 220160

__global__ __launch_bounds__(512, 1) void scan_kernel(
    const __nv_bfloat16* __restrict__ kh, const __nv_bfloat16* __restrict__ kl,
    const __nv_bfloat16* __restrict__ qh, const __nv_bfloat16* __restrict__ ql,
    const __nv_bfloat16* __restrict__ kth, const __nv_bfloat16* __restrict__ ktl,
    const float* __restrict__ v, const float* __restrict__ minv,
    const float* __restrict__ pmat, const float* __restrict__ coef,
    float* __restrict__ o)
{
    extern __shared__ char sb[];
    const uint32_t sbase = smem_to_u32(sb);
    float* M0 = (float*)(sb + SB_M0);
    float* Z0 = (float*)(sb + SB_Z0);
    float* M1 = (float*)(sb + SB_M1);
    float* Z1 = (float*)(sb + SB_Z1);
    float* Cf = (float*)(sb + SB_CF);
    float* Vb = (float*)(sb + SB_V);
    float* sMinv = (float*)(sb + SB_MINV);
    float* sRmat = (float*)(sb + SB_PMAT);
    __nv_bfloat16* Sth = (__nv_bfloat16*)(sb + SB_STH);
    __nv_bfloat16* Stl = (__nv_bfloat16*)(sb + SB_STL);
    const int blk = blockIdx.x;
    const int bh = blk >> 3, dvb = blk & 7;
    const int b = bh >> 2, h = bh & 3;
    const int colb = dvb * 32;
    const int tid = threadIdx.x, w = tid >> 5, lane = tid & 31;
    const int lrow = lane & 15, lcolb = (lane >> 4) * 16;
    const size_t rowbase = (size_t)b * Tsz * Dsz + h * DKsz;
    const size_t ktbase = (size_t)bh * DKsz * Tsz;

    for (int i = tid; i < 32 * 264; i += 512) {
        Sth[i] = __float2bfloat16(0.f);
        Stl[i] = __float2bfloat16(0.f);
    }
    __syncthreads();

    for (int chn = 0; chn < NCH; chn++) {
        const int t0 = chn * CH;
        const size_t pb = (size_t)(bh * NCH + chn) * 4096;
        if (tid < 256) Cf[tid] = coef[(size_t)(bh * NCH + chn) * 256 + tid];
        // ---- group: KQ hi/lo + v ----
#pragma unroll
        for (int r = 0; r < 8; r++) {
            int idx = r * 512 + tid;
            int rr = idx >> 5, c = idx & 31;
            const __nv_bfloat16* sh;
            const __nv_bfloat16* sl;
            if (rr < 64) {
                sh = kh + rowbase + (size_t)(t0 + rr) * Dsz + c * 8;
                sl = kl + rowbase + (size_t)(t0 + rr) * Dsz + c * 8;
            } else {
                sh = qh + rowbase + (size_t)(t0 + rr - 64) * Dsz + c * 8;
                sl = ql + rowbase + (size_t)(t0 + rr - 64) * Dsz + c * 8;
            }
            cp_async16(sbase + SB_KQ + rr * 528 + c * 16, sh);
            cp_async16(sbase + SB_KQLO + rr * 528 + c * 16, sl);
        }
        {
            int rr = tid >> 3, c4 = (tid & 7) * 4;
            cp_async16(sbase + SB_V + (rr * 32 + c4) * 4,
                       v + rowbase + (size_t)(t0 + rr) * Dsz + colb + c4);
        }
        asm volatile("cp.async.commit_group;\n\tcp.async.wait_group 0;" ::: "memory");
        __syncthreads();

        // ---- MZ GEMM split-K ----
        {
            const int mb = (w & 7) * 16;
            const int khalf = w >> 3;
            float cm[2][2][4];
#pragma unroll
            for (int nt = 0; nt < 2; nt++)
#pragma unroll
                for (int hf = 0; hf < 2; hf++)
#pragma unroll
                    for (int i = 0; i < 4; i++) cm[nt][hf][i] = 0.f;
#pragma unroll
            for (int ks8 = 0; ks8 < 8; ks8++) {
                const int ks = khalf * 8 + ks8;
                const uint32_t cb = ks * 32 + lcolb;
                uint32_t a[4], al[4], b0[4], b1[4], t[4];
                ldsm4p(a,  sbase + SB_KQ   + (mb + lrow) * 528 + cb);
                ldsm4p(al, sbase + SB_KQLO + (mb + lrow) * 528 + cb);
                ldsm4p(b0, sbase + SB_STH + (lrow) * 528 + cb);
                ldsm4p(b1, sbase + SB_STH + (16 + lrow) * 528 + cb);
                mma16816(cm[0][0], a, b0[0], b0[2]); mma16816(cm[0][1], a, b0[1], b0[3]);
                mma16816(cm[1][0], a, b1[0], b1[2]); mma16816(cm[1][1], a, b1[1], b1[3]);
                mma16816(cm[0][0], al, b0[0], b0[2]); mma16816(cm[0][1], al, b0[1], b0[3]);
                mma16816(cm[1][0], al, b1[0], b1[2]); mma16816(cm[1][1], al, b1[1], b1[3]);
                ldsm4p(t, sbase + SB_STL + (lrow) * 528 + cb);
                mma16816(cm[0][0], a, t[0], t[2]); mma16816(cm[0][1], a, t[1], t[3]);
                ldsm4p(t, sbase + SB_STL + (16 + lrow) * 528 + cb);
                mma16816(cm[1][0], a, t[0], t[2]); mma16816(cm[1][1], a, t[1], t[3]);
            }
            const int cr = mb + (lane >> 2);
            float* dst;
            if (khalf == 0) dst = (cr < 64) ? (M0 + cr * 32) : (Z0 + (cr - 64) * 32);
            else            dst = (cr < 64) ? (M1 + cr * 32) : (Z1 + (cr - 64) * 32);
#pragma unroll
            for (int nt = 0; nt < 2; nt++)
#pragma unroll
                for (int hf = 0; hf < 2; hf++) {
                    int cc0 = nt * 16 + hf * 8 + (lane & 3) * 2;
                    dst[cc0]   = cm[nt][hf][0];
                    dst[cc0+1] = cm[nt][hf][1];
                    dst[8*32 + cc0]   = cm[nt][hf][2];
                    dst[8*32 + cc0+1] = cm[nt][hf][3];
                }
        }
        __syncthreads();

        // ---- group A: minv + R ----
#pragma unroll
        for (int r = 0; r < 2; r++) {
            int idx = r * 512 + tid;
            cp_async16(sbase + SB_MINV + idx * 16, minv + pb + idx * 4);
            cp_async16(sbase + SB_PMAT + idx * 16, pmat + pb + idx * 4);
        }
        asm volatile("cp.async.commit_group;" ::: "memory");
        // ---- group B: KT ----
#pragma unroll
        for (int r = 0; r < 4; r++) {
            int idx = r * 512 + tid, rr = idx >> 3, c = idx & 7;
            cp_async16(sbase + SB_KT + rr * 144 + c * 16,
                       kth + ktbase + (size_t)rr * Tsz + t0 + c * 8);
            cp_async16(sbase + SB_KTLO + rr * 144 + c * 16,
                       ktl + ktbase + (size_t)rr * Tsz + t0 + c * 8);
        }
        asm volatile("cp.async.commit_group;" ::: "memory");

        // ---- B' = bet*v - betgam*(M0+M1) -> M0 ----
#pragma unroll
        for (int e = 0; e < 4; e++) {
            int idx = e * 512 + tid, i = idx >> 5;
            M0[idx] = Cf[i] * Vb[idx] - Cf[64 + i] * (M0[idx] + M1[idx]);
        }
        asm volatile("cp.async.wait_group 1;" ::: "memory");
        __syncthreads();

        // ---- merged UO phase (warp-specialized) ----
        if (tid < 256) {
            // O = gam*(Z0+Z1) + R*B'  -> gmem
            const int i = tid >> 2, cb8 = (tid & 3) * 8;
            const float gi = Cf[128 + i];
            float4 z0a = *(const float4*)&Z0[i*32 + cb8];
            float4 z1a = *(const float4*)&Z1[i*32 + cb8];
            float4 z0b = *(const float4*)&Z0[i*32 + cb8 + 4];
            float4 z1b = *(const float4*)&Z1[i*32 + cb8 + 4];
            float4 a0 = make_float4(gi*(z0a.x+z1a.x), gi*(z0a.y+z1a.y),
                                    gi*(z0a.z+z1a.z), gi*(z0a.w+z1a.w));
            float4 a1 = make_float4(gi*(z0b.x+z1b.x), gi*(z0b.y+z1b.y),
                                    gi*(z0b.z+z1b.z), gi*(z0b.w+z1b.w));
            const float* rrow = sRmat + i * 64;
            for (int j = 0; j < 64; j++) {
                float pv = rrow[j];
                float4 b0 = *(const float4*)&M0[j*32 + cb8];
                float4 b1 = *(const float4*)&M0[j*32 + cb8 + 4];
                a0.x += pv*b0.x; a0.y += pv*b0.y; a0.z += pv*b0.z; a0.w += pv*b0.w;
                a1.x += pv*b1.x; a1.y += pv*b1.y; a1.z += pv*b1.z; a1.w += pv*b1.w;
            }
            float* op = o + rowbase + (size_t)(t0 + i) * Dsz + colb + cb8;
            *(float4*)op = a0;
            *(float4*)(op + 4) = a1;
        } else {
            // U = Minv*B' ; pack Ut (cc-scaled) hi/lo directly
            const int t2 = tid - 256;
            const int i = t2 >> 2, cb8 = (t2 & 3) * 8;
            float4 a0 = make_float4(0,0,0,0), a1 = make_float4(0,0,0,0);
            const float* mrow = sMinv + i * 64;
            for (int j = 0; j < 64; j++) {
                float mv = mrow[j];
                float4 b0 = *(const float4*)&M0[j*32 + cb8];
                float4 b1 = *(const float4*)&M0[j*32 + cb8 + 4];
                a0.x += mv*b0.x; a0.y += mv*b0.y; a0.z += mv*b0.z; a0.w += mv*b0.w;
                a1.x += mv*b1.x; a1.y += mv*b1.y; a1.z += mv*b1.z; a1.w += mv*b1.w;
            }
            const float ci = Cf[192 + i];
            float uv[8] = {a0.x, a0.y, a0.z, a0.w, a1.x, a1.y, a1.z, a1.w};
            __nv_bfloat16* uth = (__nv_bfloat16*)(sb + SB_UTH);
            __nv_bfloat16* utl = (__nv_bfloat16*)(sb + SB_UTL);
#pragma unroll
            for (int c = 0; c < 8; c++) {
                float val = ci * uv[c];
                __nv_bfloat16 hh = __float2bfloat16(val);
                uth[(cb8 + c) * 72 + i] = hh;
                utl[(cb8 + c) * 72 + i] =
                    __float2bfloat16(val - __bfloat162float(hh));
            }
        }
        asm volatile("cp.async.wait_group 0;" ::: "memory");
        __syncthreads();

        // ---- S^T = g63*S^T + Ut * KT ----
        {
            const float g63 = Cf[128 + 63];
            const int nb = w * 16;
#pragma unroll
            for (int mt = 0; mt < 2; mt++) {
                const int mb = mt * 16;
                const int cr = mb + (lane >> 2), cc0 = nb + (lane & 3) * 2;
                float c0[4], c1[4];
#pragma unroll
                for (int e = 0; e < 8; e++) {
                    int rr = (e & 2) ? cr + 8 : cr;
                    int cc = cc0 + ((e >> 2) ? 8 : 0) + (e & 1);
                    float sv = __bfloat162float(Sth[rr*264 + cc])
                             + __bfloat162float(Stl[rr*264 + cc]);
                    if (e >> 2) c1[e & 3] = g63 * sv;
                    else        c0[e & 3] = g63 * sv;
                }
#pragma unroll
                for (int ks = 0; ks < 4; ks++) {
                    uint32_t cb = ks * 32 + lcolb;
                    uint32_t a[4], bbv[4], t[4];
                    ldsm4p(a, sbase + SB_UTH + (mb+lrow)*144 + cb);
                    ldsm4p(bbv, sbase + SB_KT + (nb+lrow)*144 + cb);
                    mma16816(c0, a, bbv[0], bbv[2]); mma16816(c1, a, bbv[1], bbv[3]);
                    ldsm4p(t, sbase + SB_UTL + (mb+lrow)*144 + cb);
                    mma16816(c0, t, bbv[0], bbv[2]); mma16816(c1, t, bbv[1], bbv[3]);
                    ldsm4p(t, sbase + SB_KTLO + (nb+lrow)*144 + cb);
                    mma16816(c0, a, t[0], t[2]); mma16816(c1, a, t[1], t[3]);
                }
#pragma unroll
                for (int e = 0; e < 8; e++) {
                    int rr = (e & 2) ? cr + 8 : cr;
                    int cc = cc0 + ((e >> 2) ? 8 : 0) + (e & 1);
                    float val = (e >> 2) ? c1[e & 3] : c0[e & 3];
                    __nv_bfloat16 hh = __float2bfloat16(val);
                    Sth[rr*264 + cc] = hh;
                    Stl[rr*264 + cc] = __float2bfloat16(val - __bfloat162float(hh));
                }
            }
        }
        __syncthreads();
    }
}

// ---- gated RMSNorm, fused hi/lo split output ----
__global__ __launch_bounds__(256) void gate_norm_split_kernel(
    const float* __restrict__ o, const float* __restrict__ g,
    const float* __restrict__ norm_w,
    __nv_bfloat16* __restrict__ yh, __nv_bfloat16* __restrict__ yl)
{
    const int row = blockIdx.x * 8 + (threadIdx.x >> 5);
    const int lane = threadIdx.x & 31;
    const float4* orow = (const float4*)(o + (size_t)row * DVsz);
    float4 o0 = orow[lane*2], o1 = orow[lane*2+1];
    float ss = o0.x*o0.x+o0.y*o0.y+o0.z*o0.z+o0.w*o0.w
             + o1.x*o1.x+o1.y*o1.y+o1.z*o1.z+o1.w*o1.w;
#pragma unroll
    for (int off = 16; off; off >>= 1)
        ss += __shfl_xor_sync(0xffffffffu, ss, off);
    float r = rsqrtf(ss * (1.f/256.f) + 1e-5f);
    const float4* nw = (const float4*)norm_w;
    float4 w0 = nw[lane*2], w1 = nw[lane*2+1];
    const float4* grow = (const float4*)(g + (size_t)row * DVsz);
    float4 g0 = grow[lane*2], g1 = grow[lane*2+1];
    float4 r0, r1;
    r0.x = o0.x*r*w0.x*(g0.x/(1.f+expf(-g0.x)));
    r0.y = o0.y*r*w0.y*(g0.y/(1.f+expf(-g0.y)));
    r0.z = o0.z*r*w0.z*(g0.z/(1.f+expf(-g0.z)));
    r0.w = o0.w*r*w0.w*(g0.w/(1.f+expf(-g0.w)));
    r1.x = o1.x*r*w1.x*(g1.x/(1.f+expf(-g1.x)));
    r1.y = o1.y*r*w1.y*(g1.y/(1.f+expf(-g1.y)));
    r1.z = o1.z*r*w1.z*(g1.z/(1.f+expf(-g1.z)));
    r1.w = o1.w*r*w1.w*(g1.w/(1.f+expf(-g1.w)));
    const size_t e0 = (size_t)row * DVsz + lane * 8;
    __nv_bfloat162 lo;
    ((__nv_bfloat162*)(yh + e0))[0] = splitpack2(r0.x, r0.y, lo); ((__nv_bfloat162*)(yl + e0))[0] = lo;
    ((__nv_bfloat162*)(yh + e0))[1] = splitpack2(r0.z, r0.w, lo); ((__nv_bfloat162*)(yl + e0))[1] = lo;
    ((__nv_bfloat162*)(yh + e0))[2] = splitpack2(r1.x, r1.y, lo); ((__nv_bfloat162*)(yl + e0))[2] = lo;
    ((__nv_bfloat162*)(yh + e0))[3] = splitpack2(r1.z, r1.w, lo); ((__nv_bfloat162*)(yl + e0))[3] = lo;
}

// ---- host ----
extern "C" void kernel_launch(void* const* d_in, const int* in_sizes, int n_in,
                              void* d_out, int out_size)
{
    const float* x       = (const float*)d_in[0];
    const float* Wq      = (const float*)d_in[1];
    const float* Wk      = (const float*)d_in[2];
    const float* Wv      = (const float*)d_in[3];
    const float* Wb      = (const float*)d_in[4];
    const float* Wa      = (const float*)d_in[5];
    const float* A_log   = (const float*)d_in[6];
    const float* dt_bias = (const float*)d_in[7];
    const float* Wg      = (const float*)d_in[8];
    const float* norm_w  = (const float*)d_in[9];
    const float* Wo      = (const float*)d_in[10];
    float* out = (float*)d_out;

    float *q,*k,*v,*g,*o,*beta,*dec,*minv,*pmat,*coef;
    cudaGetSymbolAddress((void**)&q, g_q);
    cudaGetSymbolAddress((void**)&k, g_k);
    cudaGetSymbolAddress((void**)&v, g_v);
    cudaGetSymbolAddress((void**)&g, g_g);
    cudaGetSymbolAddress((void**)&o, g_o);
    cudaGetSymbolAddress((void**)&beta, g_beta);
    cudaGetSymbolAddress((void**)&dec, g_dec);
    cudaGetSymbolAddress((void**)&minv, g_minv);
    cudaGetSymbolAddress((void**)&pmat, g_pmat);
    cudaGetSymbolAddress((void**)&coef, g_coef);
    __nv_bfloat16 *xh,*xl,*yh,*yl,*qh,*ql,*kh,*kl,*kth,*ktl,*wth,*wtl;
    cudaGetSymbolAddress((void**)&xh, g_xh);
    cudaGetSymbolAddress((void**)&xl, g_xl);
    cudaGetSymbolAddress((void**)&yh, g_yh);
    cudaGetSymbolAddress((void**)&yl, g_yl);
    cudaGetSymbolAddress((void**)&qh, g_qh);
    cudaGetSymbolAddress((void**)&ql, g_ql);
    cudaGetSymbolAddress((void**)&kh, g_kh);
    cudaGetSymbolAddress((void**)&kl, g_kl);
    cudaGetSymbolAddress((void**)&kth, g_kth);
    cudaGetSymbolAddress((void**)&ktl, g_ktl);
    cudaGetSymbolAddress((void**)&wth, g_wth);
    cudaGetSymbolAddress((void**)&wtl, g_wtl);

    cudaFuncSetAttribute(gemm_mma_bf16x3,
        cudaFuncAttributeMaxDynamicSharedMemorySize, GEMM_SMEM);
    cudaFuncSetAttribute(gemm_mega4,
        cudaFuncAttributeMaxDynamicSharedMemorySize, GEMM_SMEM);
    cudaFuncSetAttribute(ut_prep,
        cudaFuncAttributeMaxDynamicSharedMemorySize, UTP_SMEM);
    cudaFuncSetAttribute(scan_kernel,
        cudaFuncAttributeMaxDynamicSharedMemorySize, SCAN_SMEM);

    dim3 tgrid(Dsz/32, Dsz/32);
    transpose_split_kernel<<<tgrid, 256>>>(Wq, wth + 0*Dsz*Dsz, wtl + 0*Dsz*Dsz);
    transpose_split_kernel<<<tgrid, 256>>>(Wk, wth + 1*Dsz*Dsz, wtl + 1*Dsz*Dsz);
    transpose_split_kernel<<<tgrid, 256>>>(Wv, wth + 2*Dsz*Dsz, wtl + 2*Dsz*Dsz);
    transpose_split_kernel<<<tgrid, 256>>>(Wg, wth + 3*Dsz*Dsz, wtl + 3*Dsz*Dsz);
    split_kernel<<<(ROWS*Dsz/4)/256, 256>>>(x, xh, xl);

    gemm_mega4<<<dim3(32, ROWS/128), 256, GEMM_SMEM>>>(xh, xl, wth, wtl, q, k, v, g);

    transpose_split_kernel<<<tgrid, 256>>>(Wo, wth + 4*Dsz*Dsz, wtl + 4*Dsz*Dsz);
    beta_dec_kernel<<<ROWS/8, 256>>>(x, Wb, Wa, A_log, dt_bias, beta, dec);
    norm_qk_split_kernel<<<(ROWS*Hsz)/8, 256>>>(q, k, qh, ql, kh, kl);

    transpose_k_kernel<<<dim3(Tsz/32, DKsz/32, 16), 256>>>(k, kth, ktl);
    ut_prep<<<dim3(NCH, 16), 256, UTP_SMEM>>>(k, q, beta, dec, minv, pmat, coef);
    scan_kernel<<<128, 512, SCAN_SMEM>>>(kh, kl, qh, ql, kth, ktl,
                                         v, minv, pmat, coef, o);

    gate_norm_split_kernel<<<(ROWS*Hsz)/8, 256>>>(o, g, norm_w, yh, yl);
    gemm_mma_bf16x3<<<dim3(Dsz/128, ROWS/128), 256, GEMM_SMEM>>>(
        yh, yl, wth+4*Dsz*Dsz, wtl+4*Dsz*Dsz, out);
}

// round 17
// speedup vs baseline: 1.0491x; 1.0491x over previous
#include <cuda_runtime.h>
#include <cuda_bf16.h>
#include <math.h>
#include <cstdint>

#define Bsz 4
#define Tsz 4096
#define Dsz 1024
#define Hsz 4
#define DKsz 256
#define DVsz 256
#define ROWS (Bsz*Tsz)
#define CH 64
#define NCH (Tsz/CH)

// -------- static device scratch --------
__device__ float g_q[ROWS * Dsz];
__device__ float g_k[ROWS * Dsz];
__device__ float g_v[ROWS * Dsz];
__device__ float g_g[ROWS * Dsz];
__device__ float g_o[ROWS * Dsz];
__device__ float g_beta[ROWS * Hsz];
__device__ float g_dec[ROWS * Hsz];
__device__ float g_minv[16 * NCH * CH * CH];
__device__ float g_pmat[16 * NCH * CH * CH];   // holds R = P*Minv
__device__ float g_coef[16 * NCH * 256];
__device__ __nv_bfloat16 g_xh[ROWS * Dsz];
__device__ __nv_bfloat16 g_xl[ROWS * Dsz];
__device__ __nv_bfloat16 g_yh[ROWS * Dsz];
__device__ __nv_bfloat16 g_yl[ROWS * Dsz];
__device__ __nv_bfloat16 g_qh[ROWS * Dsz];
__device__ __nv_bfloat16 g_ql[ROWS * Dsz];
__device__ __nv_bfloat16 g_kh[ROWS * Dsz];
__device__ __nv_bfloat16 g_kl[ROWS * Dsz];
__device__ __nv_bfloat16 g_kth[16 * DKsz * Tsz];
__device__ __nv_bfloat16 g_ktl[16 * DKsz * Tsz];
__device__ __nv_bfloat16 g_wth[5 * Dsz * Dsz];
__device__ __nv_bfloat16 g_wtl[5 * Dsz * Dsz];

// ---- helpers ----
__device__ __forceinline__ uint32_t smem_to_u32(const void* p) {
    uint32_t a;
    asm("{ .reg .u64 t; cvta.to.shared.u64 t, %1; cvt.u32.u64 %0, t; }"
        : "=r"(a) : "l"(p));
    return a;
}
__device__ __forceinline__ void cp_async16(uint32_t s, const void* g) {
    asm volatile("cp.async.cg.shared.global [%0], [%1], 16;" :: "r"(s), "l"(g));
}
__device__ __forceinline__ void ldsm4(uint32_t& r0, uint32_t& r1, uint32_t& r2,
                                      uint32_t& r3, uint32_t addr) {
    asm volatile("ldmatrix.sync.aligned.m8n8.x4.shared.b16 {%0,%1,%2,%3}, [%4];"
                 : "=r"(r0), "=r"(r1), "=r"(r2), "=r"(r3) : "r"(addr));
}
__device__ __forceinline__ void ldsm4p(uint32_t* r, uint32_t addr) {
    ldsm4(r[0], r[1], r[2], r[3], addr);
}
__device__ __forceinline__ void mma16816(float* c, const uint32_t* a,
                                         uint32_t b0, uint32_t b1) {
    asm volatile(
        "mma.sync.aligned.m16n8k16.row.col.f32.bf16.bf16.f32 "
        "{%0,%1,%2,%3}, {%4,%5,%6,%7}, {%8,%9}, {%0,%1,%2,%3};"
        : "+f"(c[0]), "+f"(c[1]), "+f"(c[2]), "+f"(c[3])
        : "r"(a[0]), "r"(a[1]), "r"(a[2]), "r"(a[3]), "r"(b0), "r"(b1));
}
__device__ __forceinline__ __nv_bfloat162 splitpack2(float a, float b,
                                                     __nv_bfloat162& lo) {
    __nv_bfloat16 h0 = __float2bfloat16(a), h1 = __float2bfloat16(b);
    lo = __halves2bfloat162(__float2bfloat16(a - __bfloat162float(h0)),
                            __float2bfloat16(b - __bfloat162float(h1)));
    return __halves2bfloat162(h0, h1);
}

// ---- fp32 -> hi/lo bf16 split ----
__global__ __launch_bounds__(256) void split_kernel(
    const float* __restrict__ src, __nv_bfloat16* __restrict__ hi,
    __nv_bfloat16* __restrict__ lo)
{
    const int i = blockIdx.x * 256 + threadIdx.x;
    float4 v = ((const float4*)src)[i];
    __nv_bfloat162 l0, l1;
    __nv_bfloat162 h0 = splitpack2(v.x, v.y, l0);
    __nv_bfloat162 h1 = splitpack2(v.z, v.w, l1);
    ((__nv_bfloat162*)hi)[i*2]   = h0;
    ((__nv_bfloat162*)hi)[i*2+1] = h1;
    ((__nv_bfloat162*)lo)[i*2]   = l0;
    ((__nv_bfloat162*)lo)[i*2+1] = l1;
}

// ---- transpose 1024x1024 weight + split ----
__global__ __launch_bounds__(256) void transpose_split_kernel(
    const float* __restrict__ W, __nv_bfloat16* __restrict__ Th,
    __nv_bfloat16* __restrict__ Tl)
{
    __shared__ float tile[32][33];
    const int n0 = blockIdx.x * 32, k0 = blockIdx.y * 32;
    const int tx = threadIdx.x & 31, ty = threadIdx.x >> 5;
#pragma unroll
    for (int r = ty; r < 32; r += 8)
        tile[r][tx] = W[(size_t)(k0 + r) * Dsz + n0 + tx];
    __syncthreads();
#pragma unroll
    for (int r = ty; r < 32; r += 8) {
        float v = tile[tx][r];
        __nv_bfloat16 h = __float2bfloat16(v);
        __nv_bfloat16 l = __float2bfloat16(v - __bfloat162float(h));
        size_t o = (size_t)(n0 + r) * Dsz + k0 + tx;
        Th[o] = h; Tl[o] = l;
    }
}

// ---- transpose k per bh -> KT [bh][256 dk][4096 t] hi/lo bf16 ----
__global__ __launch_bounds__(256) void transpose_k_kernel(
    const float* __restrict__ k, __nv_bfloat16* __restrict__ kth,
    __nv_bfloat16* __restrict__ ktl)
{
    __shared__ float tile[32][33];
    const int tblk = blockIdx.x * 32, dkblk = blockIdx.y * 32;
    const int bh = blockIdx.z, b = bh >> 2, h = bh & 3;
    const int tx = threadIdx.x & 31, ty = threadIdx.x >> 5;
    const size_t rowbase = (size_t)b * Tsz * Dsz + h * DKsz;
#pragma unroll
    for (int r = ty; r < 32; r += 8)
        tile[r][tx] = k[rowbase + (size_t)(tblk + r) * Dsz + dkblk + tx];
    __syncthreads();
#pragma unroll
    for (int r = ty; r < 32; r += 8) {
        float v = tile[tx][r];
        __nv_bfloat16 h2 = __float2bfloat16(v);
        __nv_bfloat16 l2 = __float2bfloat16(v - __bfloat162float(h2));
        size_t o = ((size_t)bh * DKsz + dkblk + r) * Tsz + tblk + tx;
        kth[o] = h2; ktl[o] = l2;
    }
}

// ============================================================
// bf16x3 GEMM (verified R11/R12)
// ============================================================
#define TILE_BYTES (128*80)
#define STAGE_BYTES (4*TILE_BYTES)
#define GEMM_SMEM (2*STAGE_BYTES)

__device__ __forceinline__ void gemm_body(
    const __nv_bfloat16* srcA_h, const __nv_bfloat16* srcA_l,
    const __nv_bfloat16* srcB_h, const __nv_bfloat16* srcB_l,
    float* Cb, char* sm)
{
    const int tid = threadIdx.x;
    const int wid = tid >> 5, lane = tid & 31;
    const int wm = wid & 3, wn = wid >> 2;
    const uint32_t sbase = smem_to_u32(sm);
    const __nv_bfloat16* srcs[4] = { srcA_h, srcA_l, srcB_h, srcB_l };
    float acc[2][8][4];
#pragma unroll
    for (int mt = 0; mt < 2; mt++)
#pragma unroll
        for (int nt = 0; nt < 8; nt++)
#pragma unroll
            for (int i = 0; i < 4; i++) acc[mt][nt][i] = 0.f;
    auto load_stage = [&](int kc) {
        const uint32_t sdst = sbase + (kc & 1) * STAGE_BYTES;
        const int k0 = kc * 32;
#pragma unroll
        for (int t = 0; t < 4; t++) {
#pragma unroll
            for (int i = 0; i < 2; i++) {
                int id = i * 256 + tid;
                int r = id >> 2, c = id & 3;
                cp_async16(sdst + t * TILE_BYTES + r * 80 + c * 16,
                           srcs[t] + (size_t)r * Dsz + k0 + c * 8);
            }
        }
        asm volatile("cp.async.commit_group;" ::: "memory");
    };
    load_stage(0);
    const int lrow = lane & 15, lcolb = (lane >> 4) * 16;
    for (int kc = 0; kc < 32; kc++) {
        if (kc < 31) load_stage(kc + 1);
        else asm volatile("cp.async.commit_group;" ::: "memory");
        asm volatile("cp.async.wait_group 1;" ::: "memory");
        __syncthreads();
        const uint32_t s = sbase + (kc & 1) * STAGE_BYTES;
#pragma unroll
        for (int ks = 0; ks < 2; ks++) {
            const uint32_t cb = ks * 32 + lcolb;
            uint32_t ah[2][4], bh[4][4], al[2][4], bl[4][4];
#pragma unroll
            for (int mt = 0; mt < 2; mt++)
                ldsm4p(ah[mt], s + (wm * 32 + mt * 16 + lrow) * 80 + cb);
#pragma unroll
            for (int bt = 0; bt < 4; bt++)
                ldsm4p(bh[bt], s + 2*TILE_BYTES + (wn * 64 + bt * 16 + lrow) * 80 + cb);
#pragma unroll
            for (int mt = 0; mt < 2; mt++)
#pragma unroll
                for (int bt = 0; bt < 4; bt++) {
                    mma16816(acc[mt][bt*2],   ah[mt], bh[bt][0], bh[bt][2]);
                    mma16816(acc[mt][bt*2+1], ah[mt], bh[bt][1], bh[bt][3]);
                }
#pragma unroll
            for (int mt = 0; mt < 2; mt++)
                ldsm4p(al[mt], s + TILE_BYTES + (wm * 32 + mt * 16 + lrow) * 80 + cb);
#pragma unroll
            for (int mt = 0; mt < 2; mt++)
#pragma unroll
                for (int bt = 0; bt < 4; bt++) {
                    mma16816(acc[mt][bt*2],   al[mt], bh[bt][0], bh[bt][2]);
                    mma16816(acc[mt][bt*2+1], al[mt], bh[bt][1], bh[bt][3]);
                }
#pragma unroll
            for (int bt = 0; bt < 4; bt++)
                ldsm4p(bl[bt], s + 3*TILE_BYTES + (wn * 64 + bt * 16 + lrow) * 80 + cb);
#pragma unroll
            for (int mt = 0; mt < 2; mt++)
#pragma unroll
                for (int bt = 0; bt < 4; bt++) {
                    mma16816(acc[mt][bt*2],   ah[mt], bl[bt][0], bl[bt][2]);
                    mma16816(acc[mt][bt*2+1], ah[mt], bl[bt][1], bl[bt][3]);
                }
        }
        __syncthreads();
    }
    const int crow = wm * 32 + (lane >> 2);
    const int ccol = wn * 64 + (lane & 3) * 2;
#pragma unroll
    for (int mt = 0; mt < 2; mt++)
#pragma unroll
        for (int nt = 0; nt < 8; nt++) {
            float* p0 = Cb + (size_t)(crow + mt * 16) * Dsz + ccol + nt * 8;
            *(float2*)p0 = make_float2(acc[mt][nt][0], acc[mt][nt][1]);
            *(float2*)(p0 + 8 * Dsz) = make_float2(acc[mt][nt][2], acc[mt][nt][3]);
        }
}

__global__ __launch_bounds__(256, 2) void gemm_mma_bf16x3(
    const __nv_bfloat16* __restrict__ Ah, const __nv_bfloat16* __restrict__ Al,
    const __nv_bfloat16* __restrict__ Bh, const __nv_bfloat16* __restrict__ Bl,
    float* __restrict__ C)
{
    extern __shared__ char sm[];
    const int bx = blockIdx.x, by = blockIdx.y;
    gemm_body(Ah + (size_t)(by * 128) * Dsz, Al + (size_t)(by * 128) * Dsz,
              Bh + (size_t)(bx * 128) * Dsz, Bl + (size_t)(bx * 128) * Dsz,
              C + (size_t)(by * 128) * Dsz + bx * 128, sm);
}

__global__ __launch_bounds__(256, 2) void gemm_mega4(
    const __nv_bfloat16* __restrict__ Ah, const __nv_bfloat16* __restrict__ Al,
    const __nv_bfloat16* __restrict__ Wth, const __nv_bfloat16* __restrict__ Wtl,
    float* __restrict__ C0, float* __restrict__ C1,
    float* __restrict__ C2, float* __restrict__ C3)
{
    extern __shared__ char sm[];
    const int bx = blockIdx.x, by = blockIdx.y;
    const int m = bx >> 3, bxl = bx & 7;
    float* Cm = (m == 0) ? C0 : (m == 1) ? C1 : (m == 2) ? C2 : C3;
    const size_t woff = (size_t)m * Dsz * Dsz + (size_t)(bxl * 128) * Dsz;
    gemm_body(Ah + (size_t)(by * 128) * Dsz, Al + (size_t)(by * 128) * Dsz,
              Wth + woff, Wtl + woff,
              Cm + (size_t)(by * 128) * Dsz + bxl * 128, sm);
}

// ---- beta/dec ----
__global__ __launch_bounds__(256) void beta_dec_kernel(
    const float* __restrict__ x, const float* __restrict__ Wb,
    const float* __restrict__ Wa, const float* __restrict__ A_log,
    const float* __restrict__ dt_bias,
    float* __restrict__ beta, float* __restrict__ dec)
{
    const int row = blockIdx.x * 8 + (threadIdx.x >> 5);
    const int lane = threadIdx.x & 31;
    float accb[4] = {0,0,0,0}, acca[4] = {0,0,0,0};
    const float* xr = x + (size_t)row * Dsz;
    const float4* Wb4 = (const float4*)Wb;
    const float4* Wa4 = (const float4*)Wa;
    for (int i = lane; i < Dsz; i += 32) {
        float xv = xr[i];
        float4 wb = Wb4[i], wa = Wa4[i];
        accb[0] += xv*wb.x; accb[1] += xv*wb.y; accb[2] += xv*wb.z; accb[3] += xv*wb.w;
        acca[0] += xv*wa.x; acca[1] += xv*wa.y; acca[2] += xv*wa.z; acca[3] += xv*wa.w;
    }
#pragma unroll
    for (int off = 16; off; off >>= 1)
#pragma unroll
        for (int h = 0; h < 4; h++) {
            accb[h] += __shfl_xor_sync(0xffffffffu, accb[h], off);
            acca[h] += __shfl_xor_sync(0xffffffffu, acca[h], off);
        }
    if (lane < 4) {
        int h = lane;
        float bv = 1.f / (1.f + expf(-accb[h]));
        float a = acca[h] + dt_bias[h];
        float sp = fmaxf(a, 0.f) + log1pf(expf(-fabsf(a)));
        beta[(size_t)row * Hsz + h] = bv;
        dec [(size_t)row * Hsz + h] = expf(-expf(A_log[h]) * sp);
    }
}

// ---- L2 norm q/k, fused hi/lo bf16 split output ----
__global__ __launch_bounds__(256) void norm_qk_split_kernel(
    float* __restrict__ q, float* __restrict__ k,
    __nv_bfloat16* __restrict__ qh, __nv_bfloat16* __restrict__ ql,
    __nv_bfloat16* __restrict__ kh, __nv_bfloat16* __restrict__ kl)
{
    const int row = blockIdx.x * 8 + (threadIdx.x >> 5);
    const int lane = threadIdx.x & 31;
    float4* qr = (float4*)(q + (size_t)row * DKsz);
    float4* kr = (float4*)(k + (size_t)row * DKsz);
    float4 q0 = qr[lane*2], q1 = qr[lane*2+1], k0 = kr[lane*2], k1 = kr[lane*2+1];
    float sq = q0.x*q0.x+q0.y*q0.y+q0.z*q0.z+q0.w*q0.w+q1.x*q1.x+q1.y*q1.y+q1.z*q1.z+q1.w*q1.w;
    float sk = k0.x*k0.x+k0.y*k0.y+k0.z*k0.z+k0.w*k0.w+k1.x*k1.x+k1.y*k1.y+k1.z*k1.z+k1.w*k1.w;
#pragma unroll
    for (int off = 16; off; off >>= 1) {
        sq += __shfl_xor_sync(0xffffffffu, sq, off);
        sk += __shfl_xor_sync(0xffffffffu, sk, off);
    }
    float qs = rsqrtf(sq + 1e-6f) * 0.0625f;
    float ks = rsqrtf(sk + 1e-6f);
    q0.x*=qs;q0.y*=qs;q0.z*=qs;q0.w*=qs; q1.x*=qs;q1.y*=qs;q1.z*=qs;q1.w*=qs;
    k0.x*=ks;k0.y*=ks;k0.z*=ks;k0.w*=ks; k1.x*=ks;k1.y*=ks;k1.z*=ks;k1.w*=ks;
    qr[lane*2]=q0; qr[lane*2+1]=q1; kr[lane*2]=k0; kr[lane*2+1]=k1;
    const size_t e0 = (size_t)row * DKsz + lane * 8;
    __nv_bfloat162 lo;
    ((__nv_bfloat162*)(qh + e0))[0] = splitpack2(q0.x, q0.y, lo); ((__nv_bfloat162*)(ql + e0))[0] = lo;
    ((__nv_bfloat162*)(qh + e0))[1] = splitpack2(q0.z, q0.w, lo); ((__nv_bfloat162*)(ql + e0))[1] = lo;
    ((__nv_bfloat162*)(qh + e0))[2] = splitpack2(q1.x, q1.y, lo); ((__nv_bfloat162*)(ql + e0))[2] = lo;
    ((__nv_bfloat162*)(qh + e0))[3] = splitpack2(q1.z, q1.w, lo); ((__nv_bfloat162*)(ql + e0))[3] = lo;
    ((__nv_bfloat162*)(kh + e0))[0] = splitpack2(k0.x, k0.y, lo); ((__nv_bfloat162*)(kl + e0))[0] = lo;
    ((__nv_bfloat162*)(kh + e0))[1] = splitpack2(k0.z, k0.w, lo); ((__nv_bfloat162*)(kl + e0))[1] = lo;
    ((__nv_bfloat162*)(kh + e0))[2] = splitpack2(k1.x, k1.y, lo); ((__nv_bfloat162*)(kl + e0))[2] = lo;
    ((__nv_bfloat162*)(kh + e0))[3] = splitpack2(k1.z, k1.w, lo); ((__nv_bfloat162*)(kl + e0))[3] = lo;
}

// ============================================================
// Kernel A: UT-transform precompute + R = P*Minv fusion (R16, verified)
// ============================================================
#define UTP_SMEM 164352
__device__ __forceinline__ int swz(int row, int f4i) {
    return row * 64 + (f4i ^ ((row >> 2) & 7));
}
__global__ __launch_bounds__(256) void ut_prep(
    const float* __restrict__ k, const float* __restrict__ q,
    const float* __restrict__ beta, const float* __restrict__ dec,
    float* __restrict__ minv, float* __restrict__ pmat, float* __restrict__ coef)
{
    extern __shared__ float sA[];
    float* sk = sA;
    float* sq = sA + 16384;
    float* w1 = sA + 32768;
    float* w2 = w1 + 4096;
    float* sdec = w2 + 4096;
    float* sbeta = sdec + 64;
    float* sP = sA;
    const int ch = blockIdx.x, bh = blockIdx.y;
    const int b = bh >> 2, h = bh & 3;
    const int tid = threadIdx.x, t0 = ch * CH;
    const size_t rowbase = (size_t)b * Tsz * Dsz + h * DKsz;
#pragma unroll
    for (int r = 0; r < 16; r++) {
        int idx = r * 256 + tid;
        int row = idx >> 6, f4i = idx & 63;
        float4 kv = *(const float4*)(k + rowbase + (size_t)(t0+row)*Dsz + f4i*4);
        float4 qv = *(const float4*)(q + rowbase + (size_t)(t0+row)*Dsz + f4i*4);
        *(float4*)&sk[swz(row, f4i)*4] = kv;
        *(float4*)&sq[swz(row, f4i)*4] = qv;
    }
    if (tid < CH) {
        size_t bidx = (size_t)(b * Tsz + t0 + tid) * Hsz + h;
        sdec[tid] = dec[bidx];
        sbeta[tid] = beta[bidx];
    }
    __syncthreads();
    {
        const int i0 = (tid >> 4) * 4, j0 = (tid & 15) * 4;
        float aK[4][4] = {}, aQ[4][4] = {};
        for (int cc = 0; cc < 64; cc++) {
            float4 kj[4], ki[4], qi[4];
#pragma unroll
            for (int a = 0; a < 4; a++) {
                kj[a] = *(const float4*)&sk[swz(j0+a, cc)*4];
                ki[a] = *(const float4*)&sk[swz(i0+a, cc)*4];
                qi[a] = *(const float4*)&sq[swz(i0+a, cc)*4];
            }
#pragma unroll
            for (int a = 0; a < 4; a++)
#pragma unroll
                for (int bb = 0; bb < 4; bb++) {
                    aK[a][bb] += ki[a].x*kj[bb].x + ki[a].y*kj[bb].y
                               + ki[a].z*kj[bb].z + ki[a].w*kj[bb].w;
                    aQ[a][bb] += qi[a].x*kj[bb].x + qi[a].y*kj[bb].y
                               + qi[a].z*kj[bb].z + qi[a].w*kj[bb].w;
                }
        }
        __syncthreads();
#pragma unroll
        for (int a = 0; a < 4; a++)
#pragma unroll
            for (int bb = 0; bb < 4; bb++) {
                w1[(i0+a)*64 + j0+bb] = aK[a][bb];
                w2[(i0+a)*64 + j0+bb] = aQ[a][bb];
            }
    }
    __syncthreads();
    if (tid < CH) {
        const int i = tid;
        const float bi = sbeta[i];
        float gam = 1.f;
        for (int m = 0; m <= i; m++) gam *= sdec[m];
        float ccv = 1.f;
        for (int m = i + 1; m < CH; m++) ccv *= sdec[m];
        float* cf = coef + (size_t)(bh * NCH + ch) * 256;
        cf[i] = bi; cf[64+i] = bi * gam; cf[128+i] = gam; cf[192+i] = ccv;
        float ratio = 1.f;
        for (int j = i; j >= 0; j--) {
            if (j < i) ratio *= sdec[j + 1];
            sP[i*65 + j] = ratio * w2[i*64 + j];
            w1[i*64 + j] = (j < i) ? (-bi * ratio * w1[i*64 + j]) : 0.f;
        }
        for (int j = i + 1; j < CH; j++) sP[i*65 + j] = 0.f;
    }
    __syncthreads();
    if (tid < CH) {
        const int j = tid;
        for (int i = 0; i < j; i++) w2[i*64 + j] = 0.f;
        w2[j*64 + j] = 1.f;
        for (int i = j + 1; i < CH; i++) {
            float s = w1[i*64 + j];
            for (int m = j + 1; m < i; m++) s += w1[i*64 + m] * w2[m*64 + j];
            w2[i*64 + j] = s;
        }
    }
    __syncthreads();
    {
        const int i = tid >> 2;
        const int j0 = (tid & 3) * 16;
        float racc[16];
#pragma unroll
        for (int c = 0; c < 16; c++) racc[c] = 0.f;
        for (int m = 0; m < 64; m++) {
            float pv = sP[i*65 + m];
            const float* mrow = &w2[m*64 + j0];
#pragma unroll
            for (int c = 0; c < 16; c++) racc[c] += pv * mrow[c];
        }
        float* prow = pmat + (size_t)(bh * NCH + ch) * 4096 + i * 64 + j0;
#pragma unroll
        for (int c = 0; c < 16; c++) prow[c] = racc[c];
    }
#pragma unroll
    for (int r = 0; r < 16; r++) {
        int idx = r * 256 + tid;
        minv[(size_t)(bh * NCH + ch) * 4096 + idx] = w2[idx];
    }
}

// ============================================================
// Kernel B: 512-thread serial chunk scan; single fused O+U phase
// (O and U share the M0 reads; U packed to Ut hi/lo from regs).
// ============================================================
#define SB_STH  0
#define SB_STL  16896
#define SB_KQ   33792
#define SB_KQLO (SB_KQ + 67584)
#define SB_KT   SB_KQ
#define SB_KTLO (SB_KQ + 36864)
#define SB_MINV (SB_KQ + 73728)
#define SB_PMAT (SB_KQ + 90112)
#define SB_M0   168960
#define SB_Z0   177152
#define SB_M1   185344
#define SB_Z1   193536
#define SB_UTH  201728
#define SB_UTL  206336
#define SB_CF   210944
#define SB_V    211968
#define SCAN_SMEM 220160

__global__ __launch_bounds__(512, 1) void scan_kernel(
    const __nv_bfloat16* __restrict__ kh, const __nv_bfloat16* __restrict__ kl,
    const __nv_bfloat16* __restrict__ qh, const __nv_bfloat16* __restrict__ ql,
    const __nv_bfloat16* __restrict__ kth, const __nv_bfloat16* __restrict__ ktl,
    const float* __restrict__ v, const float* __restrict__ minv,
    const float* __restrict__ pmat, const float* __restrict__ coef,
    float* __restrict__ o)
{
    extern __shared__ char sb[];
    const uint32_t sbase = smem_to_u32(sb);
    float* M0 = (float*)(sb + SB_M0);
    float* Z0 = (float*)(sb + SB_Z0);
    float* M1 = (float*)(sb + SB_M1);
    float* Z1 = (float*)(sb + SB_Z1);
    float* Cf = (float*)(sb + SB_CF);
    float* Vb = (float*)(sb + SB_V);
    float* sMinv = (float*)(sb + SB_MINV);
    float* sRmat = (float*)(sb + SB_PMAT);
    __nv_bfloat16* Sth = (__nv_bfloat16*)(sb + SB_STH);
    __nv_bfloat16* Stl = (__nv_bfloat16*)(sb + SB_STL);
    const int blk = blockIdx.x;
    const int bh = blk >> 3, dvb = blk & 7;
    const int b = bh >> 2, h = bh & 3;
    const int colb = dvb * 32;
    const int tid = threadIdx.x, w = tid >> 5, lane = tid & 31;
    const int lrow = lane & 15, lcolb = (lane >> 4) * 16;
    const size_t rowbase = (size_t)b * Tsz * Dsz + h * DKsz;
    const size_t ktbase = (size_t)bh * DKsz * Tsz;

    for (int i = tid; i < 32 * 264; i += 512) {
        Sth[i] = __float2bfloat16(0.f);
        Stl[i] = __float2bfloat16(0.f);
    }
    __syncthreads();

    for (int chn = 0; chn < NCH; chn++) {
        const int t0 = chn * CH;
        const size_t pb = (size_t)(bh * NCH + chn) * 4096;
        if (tid < 256) Cf[tid] = coef[(size_t)(bh * NCH + chn) * 256 + tid];
        // ---- group: KQ hi/lo + v ----
#pragma unroll
        for (int r = 0; r < 8; r++) {
            int idx = r * 512 + tid;
            int rr = idx >> 5, c = idx & 31;
            const __nv_bfloat16* sh;
            const __nv_bfloat16* sl;
            if (rr < 64) {
                sh = kh + rowbase + (size_t)(t0 + rr) * Dsz + c * 8;
                sl = kl + rowbase + (size_t)(t0 + rr) * Dsz + c * 8;
            } else {
                sh = qh + rowbase + (size_t)(t0 + rr - 64) * Dsz + c * 8;
                sl = ql + rowbase + (size_t)(t0 + rr - 64) * Dsz + c * 8;
            }
            cp_async16(sbase + SB_KQ + rr * 528 + c * 16, sh);
            cp_async16(sbase + SB_KQLO + rr * 528 + c * 16, sl);
        }
        {
            int rr = tid >> 3, c4 = (tid & 7) * 4;
            cp_async16(sbase + SB_V + (rr * 32 + c4) * 4,
                       v + rowbase + (size_t)(t0 + rr) * Dsz + colb + c4);
        }
        asm volatile("cp.async.commit_group;\n\tcp.async.wait_group 0;" ::: "memory");
        __syncthreads();

        // ---- MZ GEMM split-K ----
        {
            const int mb = (w & 7) * 16;
            const int khalf = w >> 3;
            float cm[2][2][4];
#pragma unroll
            for (int nt = 0; nt < 2; nt++)
#pragma unroll
                for (int hf = 0; hf < 2; hf++)
#pragma unroll
                    for (int i = 0; i < 4; i++) cm[nt][hf][i] = 0.f;
#pragma unroll
            for (int ks8 = 0; ks8 < 8; ks8++) {
                const int ks = khalf * 8 + ks8;
                const uint32_t cb = ks * 32 + lcolb;
                uint32_t a[4], al[4], b0[4], b1[4], t[4];
                ldsm4p(a,  sbase + SB_KQ   + (mb + lrow) * 528 + cb);
                ldsm4p(al, sbase + SB_KQLO + (mb + lrow) * 528 + cb);
                ldsm4p(b0, sbase + SB_STH + (lrow) * 528 + cb);
                ldsm4p(b1, sbase + SB_STH + (16 + lrow) * 528 + cb);
                mma16816(cm[0][0], a, b0[0], b0[2]); mma16816(cm[0][1], a, b0[1], b0[3]);
                mma16816(cm[1][0], a, b1[0], b1[2]); mma16816(cm[1][1], a, b1[1], b1[3]);
                mma16816(cm[0][0], al, b0[0], b0[2]); mma16816(cm[0][1], al, b0[1], b0[3]);
                mma16816(cm[1][0], al, b1[0], b1[2]); mma16816(cm[1][1], al, b1[1], b1[3]);
                ldsm4p(t, sbase + SB_STL + (lrow) * 528 + cb);
                mma16816(cm[0][0], a, t[0], t[2]); mma16816(cm[0][1], a, t[1], t[3]);
                ldsm4p(t, sbase + SB_STL + (16 + lrow) * 528 + cb);
                mma16816(cm[1][0], a, t[0], t[2]); mma16816(cm[1][1], a, t[1], t[3]);
            }
            const int cr = mb + (lane >> 2);
            float* dst;
            if (khalf == 0) dst = (cr < 64) ? (M0 + cr * 32) : (Z0 + (cr - 64) * 32);
            else            dst = (cr < 64) ? (M1 + cr * 32) : (Z1 + (cr - 64) * 32);
#pragma unroll
            for (int nt = 0; nt < 2; nt++)
#pragma unroll
                for (int hf = 0; hf < 2; hf++) {
                    int cc0 = nt * 16 + hf * 8 + (lane & 3) * 2;
                    dst[cc0]   = cm[nt][hf][0];
                    dst[cc0+1] = cm[nt][hf][1];
                    dst[8*32 + cc0]   = cm[nt][hf][2];
                    dst[8*32 + cc0+1] = cm[nt][hf][3];
                }
        }
        __syncthreads();

        // ---- group A: minv + R ----
#pragma unroll
        for (int r = 0; r < 2; r++) {
            int idx = r * 512 + tid;
            cp_async16(sbase + SB_MINV + idx * 16, minv + pb + idx * 4);
            cp_async16(sbase + SB_PMAT + idx * 16, pmat + pb + idx * 4);
        }
        asm volatile("cp.async.commit_group;" ::: "memory");
        // ---- group B: KT ----
#pragma unroll
        for (int r = 0; r < 4; r++) {
            int idx = r * 512 + tid, rr = idx >> 3, c = idx & 7;
            cp_async16(sbase + SB_KT + rr * 144 + c * 16,
                       kth + ktbase + (size_t)rr * Tsz + t0 + c * 8);
            cp_async16(sbase + SB_KTLO + rr * 144 + c * 16,
                       ktl + ktbase + (size_t)rr * Tsz + t0 + c * 8);
        }
        asm volatile("cp.async.commit_group;" ::: "memory");

        // ---- B' = bet*v - betgam*(M0+M1) -> M0 ----
#pragma unroll
        for (int e = 0; e < 4; e++) {
            int idx = e * 512 + tid, i = idx >> 5;
            M0[idx] = Cf[i] * Vb[idx] - Cf[64 + i] * (M0[idx] + M1[idx]);
        }
        asm volatile("cp.async.wait_group 1;" ::: "memory");
        __syncthreads();

        // ---- fused O + U phase (all 512 threads, shared M0 reads) ----
        {
            const int i = tid >> 3, cb4 = (tid & 7) * 4;
            const float gi = Cf[128 + i];
            float4 z0 = *(const float4*)&Z0[i*32 + cb4];
            float4 z1 = *(const float4*)&Z1[i*32 + cb4];
            float4 oa = make_float4(gi*(z0.x+z1.x), gi*(z0.y+z1.y),
                                    gi*(z0.z+z1.z), gi*(z0.w+z1.w));
            float4 ua = make_float4(0,0,0,0);
            const float* rrow = sRmat + i * 64;
            const float* mrow = sMinv + i * 64;
            for (int j = 0; j < 64; j++) {
                float4 m4 = *(const float4*)&M0[j*32 + cb4];
                float rv = rrow[j], mv = mrow[j];
                oa.x += rv*m4.x; oa.y += rv*m4.y; oa.z += rv*m4.z; oa.w += rv*m4.w;
                ua.x += mv*m4.x; ua.y += mv*m4.y; ua.z += mv*m4.z; ua.w += mv*m4.w;
            }
            float* op = o + rowbase + (size_t)(t0 + i) * Dsz + colb + cb4;
            *(float4*)op = oa;
            const float ci = Cf[192 + i];
            float uv[4] = {ua.x, ua.y, ua.z, ua.w};
            __nv_bfloat16* uth = (__nv_bfloat16*)(sb + SB_UTH);
            __nv_bfloat16* utl = (__nv_bfloat16*)(sb + SB_UTL);
#pragma unroll
            for (int c = 0; c < 4; c++) {
                float val = ci * uv[c];
                __nv_bfloat16 hh = __float2bfloat16(val);
                uth[(cb4 + c) * 72 + i] = hh;
                utl[(cb4 + c) * 72 + i] =
                    __float2bfloat16(val - __bfloat162float(hh));
            }
        }
        asm volatile("cp.async.wait_group 0;" ::: "memory");
        __syncthreads();

        // ---- S^T = g63*S^T + Ut * KT ----
        {
            const float g63 = Cf[128 + 63];
            const int nb = w * 16;
#pragma unroll
            for (int mt = 0; mt < 2; mt++) {
                const int mb = mt * 16;
                const int cr = mb + (lane >> 2), cc0 = nb + (lane & 3) * 2;
                float c0[4], c1[4];
#pragma unroll
                for (int e = 0; e < 8; e++) {
                    int rr = (e & 2) ? cr + 8 : cr;
                    int cc = cc0 + ((e >> 2) ? 8 : 0) + (e & 1);
                    float sv = __bfloat162float(Sth[rr*264 + cc])
                             + __bfloat162float(Stl[rr*264 + cc]);
                    if (e >> 2) c1[e & 3] = g63 * sv;
                    else        c0[e & 3] = g63 * sv;
                }
#pragma unroll
                for (int ks = 0; ks < 4; ks++) {
                    uint32_t cb = ks * 32 + lcolb;
                    uint32_t a[4], bbv[4], t[4];
                    ldsm4p(a, sbase + SB_UTH + (mb+lrow)*144 + cb);
                    ldsm4p(bbv, sbase + SB_KT + (nb+lrow)*144 + cb);
                    mma16816(c0, a, bbv[0], bbv[2]); mma16816(c1, a, bbv[1], bbv[3]);
                    ldsm4p(t, sbase + SB_UTL + (mb+lrow)*144 + cb);
                    mma16816(c0, t, bbv[0], bbv[2]); mma16816(c1, t, bbv[1], bbv[3]);
                    ldsm4p(t, sbase + SB_KTLO + (nb+lrow)*144 + cb);
                    mma16816(c0, a, t[0], t[2]); mma16816(c1, a, t[1], t[3]);
                }
#pragma unroll
                for (int e = 0; e < 8; e++) {
                    int rr = (e & 2) ? cr + 8 : cr;
                    int cc = cc0 + ((e >> 2) ? 8 : 0) + (e & 1);
                    float val = (e >> 2) ? c1[e & 3] : c0[e & 3];
                    __nv_bfloat16 hh = __float2bfloat16(val);
                    Sth[rr*264 + cc] = hh;
                    Stl[rr*264 + cc] = __float2bfloat16(val - __bfloat162float(hh));
                }
            }
        }
        __syncthreads();
    }
}

// ---- gated RMSNorm, fused hi/lo split output ----
__global__ __launch_bounds__(256) void gate_norm_split_kernel(
    const float* __restrict__ o, const float* __restrict__ g,
    const float* __restrict__ norm_w,
    __nv_bfloat16* __restrict__ yh, __nv_bfloat16* __restrict__ yl)
{
    const int row = blockIdx.x * 8 + (threadIdx.x >> 5);
    const int lane = threadIdx.x & 31;
    const float4* orow = (const float4*)(o + (size_t)row * DVsz);
    float4 o0 = orow[lane*2], o1 = orow[lane*2+1];
    float ss = o0.x*o0.x+o0.y*o0.y+o0.z*o0.z+o0.w*o0.w
             + o1.x*o1.x+o1.y*o1.y+o1.z*o1.z+o1.w*o1.w;
#pragma unroll
    for (int off = 16; off; off >>= 1)
        ss += __shfl_xor_sync(0xffffffffu, ss, off);
    float r = rsqrtf(ss * (1.f/256.f) + 1e-5f);
    const float4* nw = (const float4*)norm_w;
    float4 w0 = nw[lane*2], w1 = nw[lane*2+1];
    const float4* grow = (const float4*)(g + (size_t)row * DVsz);
    float4 g0 = grow[lane*2], g1 = grow[lane*2+1];
    float4 r0, r1;
    r0.x = o0.x*r*w0.x*(g0.x/(1.f+expf(-g0.x)));
    r0.y = o0.y*r*w0.y*(g0.y/(1.f+expf(-g0.y)));
    r0.z = o0.z*r*w0.z*(g0.z/(1.f+expf(-g0.z)));
    r0.w = o0.w*r*w0.w*(g0.w/(1.f+expf(-g0.w)));
    r1.x = o1.x*r*w1.x*(g1.x/(1.f+expf(-g1.x)));
    r1.y = o1.y*r*w1.y*(g1.y/(1.f+expf(-g1.y)));
    r1.z = o1.z*r*w1.z*(g1.z/(1.f+expf(-g1.z)));
    r1.w = o1.w*r*w1.w*(g1.w/(1.f+expf(-g1.w)));
    const size_t e0 = (size_t)row * DVsz + lane * 8;
    __nv_bfloat162 lo;
    ((__nv_bfloat162*)(yh + e0))[0] = splitpack2(r0.x, r0.y, lo); ((__nv_bfloat162*)(yl + e0))[0] = lo;
    ((__nv_bfloat162*)(yh + e0))[1] = splitpack2(r0.z, r0.w, lo); ((__nv_bfloat162*)(yl + e0))[1] = lo;
    ((__nv_bfloat162*)(yh + e0))[2] = splitpack2(r1.x, r1.y, lo); ((__nv_bfloat162*)(yl + e0))[2] = lo;
    ((__nv_bfloat162*)(yh + e0))[3] = splitpack2(r1.z, r1.w, lo); ((__nv_bfloat162*)(yl + e0))[3] = lo;
}

// ---- host ----
extern "C" void kernel_launch(void* const* d_in, const int* in_sizes, int n_in,
                              void* d_out, int out_size)
{
    const float* x       = (const float*)d_in[0];
    const float* Wq      = (const float*)d_in[1];
    const float* Wk      = (const float*)d_in[2];
    const float* Wv      = (const float*)d_in[3];
    const float* Wb      = (const float*)d_in[4];
    const float* Wa      = (const float*)d_in[5];
    const float* A_log   = (const float*)d_in[6];
    const float* dt_bias = (const float*)d_in[7];
    const float* Wg      = (const float*)d_in[8];
    const float* norm_w  = (const float*)d_in[9];
    const float* Wo      = (const float*)d_in[10];
    float* out = (float*)d_out;

    float *q,*k,*v,*g,*o,*beta,*dec,*minv,*pmat,*coef;
    cudaGetSymbolAddress((void**)&q, g_q);
    cudaGetSymbolAddress((void**)&k, g_k);
    cudaGetSymbolAddress((void**)&v, g_v);
    cudaGetSymbolAddress((void**)&g, g_g);
    cudaGetSymbolAddress((void**)&o, g_o);
    cudaGetSymbolAddress((void**)&beta, g_beta);
    cudaGetSymbolAddress((void**)&dec, g_dec);
    cudaGetSymbolAddress((void**)&minv, g_minv);
    cudaGetSymbolAddress((void**)&pmat, g_pmat);
    cudaGetSymbolAddress((void**)&coef, g_coef);
    __nv_bfloat16 *xh,*xl,*yh,*yl,*qh,*ql,*kh,*kl,*kth,*ktl,*wth,*wtl;
    cudaGetSymbolAddress((void**)&xh, g_xh);
    cudaGetSymbolAddress((void**)&xl, g_xl);
    cudaGetSymbolAddress((void**)&yh, g_yh);
    cudaGetSymbolAddress((void**)&yl, g_yl);
    cudaGetSymbolAddress((void**)&qh, g_qh);
    cudaGetSymbolAddress((void**)&ql, g_ql);
    cudaGetSymbolAddress((void**)&kh, g_kh);
    cudaGetSymbolAddress((void**)&kl, g_kl);
    cudaGetSymbolAddress((void**)&kth, g_kth);
    cudaGetSymbolAddress((void**)&ktl, g_ktl);
    cudaGetSymbolAddress((void**)&wth, g_wth);
    cudaGetSymbolAddress((void**)&wtl, g_wtl);

    cudaFuncSetAttribute(gemm_mma_bf16x3,
        cudaFuncAttributeMaxDynamicSharedMemorySize, GEMM_SMEM);
    cudaFuncSetAttribute(gemm_mega4,
        cudaFuncAttributeMaxDynamicSharedMemorySize, GEMM_SMEM);
    cudaFuncSetAttribute(ut_prep,
        cudaFuncAttributeMaxDynamicSharedMemorySize, UTP_SMEM);
    cudaFuncSetAttribute(scan_kernel,
        cudaFuncAttributeMaxDynamicSharedMemorySize, SCAN_SMEM);

    dim3 tgrid(Dsz/32, Dsz/32);
    transpose_split_kernel<<<tgrid, 256>>>(Wq, wth + 0*Dsz*Dsz, wtl + 0*Dsz*Dsz);
    transpose_split_kernel<<<tgrid, 256>>>(Wk, wth + 1*Dsz*Dsz, wtl + 1*Dsz*Dsz);
    transpose_split_kernel<<<tgrid, 256>>>(Wv, wth + 2*Dsz*Dsz, wtl + 2*Dsz*Dsz);
    transpose_split_kernel<<<tgrid, 256>>>(Wg, wth + 3*Dsz*Dsz, wtl + 3*Dsz*Dsz);
    split_kernel<<<(ROWS*Dsz/4)/256, 256>>>(x, xh, xl);

    gemm_mega4<<<dim3(32, ROWS/128), 256, GEMM_SMEM>>>(xh, xl, wth, wtl, q, k, v, g);

    transpose_split_kernel<<<tgrid, 256>>>(Wo, wth + 4*Dsz*Dsz, wtl + 4*Dsz*Dsz);
    beta_dec_kernel<<<ROWS/8, 256>>>(x, Wb, Wa, A_log, dt_bias, beta, dec);
    norm_qk_split_kernel<<<(ROWS*Hsz)/8, 256>>>(q, k, qh, ql, kh, kl);

    transpose_k_kernel<<<dim3(Tsz/32, DKsz/32, 16), 256>>>(k, kth, ktl);
    ut_prep<<<dim3(NCH, 16), 256, UTP_SMEM>>>(k, q, beta, dec, minv, pmat, coef);
    scan_kernel<<<128, 512, SCAN_SMEM>>>(kh, kl, qh, ql, kth, ktl,
                                         v, minv, pmat, coef, o);

    gate_norm_split_kernel<<<(ROWS*Hsz)/8, 256>>>(o, g, norm_w, yh, yl);
    gemm_mma_bf16x3<<<dim3(Dsz/128, ROWS/128), 256, GEMM_SMEM>>>(
        yh, yl, wth+4*Dsz*Dsz, wtl+4*Dsz*Dsz, out);
}